// round 1
// baseline (speedup 1.0000x reference)
#include <cuda_runtime.h>

// GatedCNNLayer: X (16,4096,1024) f32, G (1024,2) f32, Gb (2,) f32
// out[b,p,:] = X[b,2p,:]*g0 + X[b,2p+2,:]*g1,
//   g = softmax(X[b,2p+1,:] @ G + Gb), p in [0,2047)
// HBM-bound streaming kernel: one block per (b,p), 256 threads, float4.

#define BATCH 16
#define SEQ   4096
#define DIM   1024
#define PAIRS 2047   // (SEQ-2)/2 + 1... actually (4096-2+1)/2 rounded: indices 0..2046

__global__ __launch_bounds__(256, 8)
void gated_cnn_kernel(const float* __restrict__ X,
                      const float* __restrict__ G,
                      const float* __restrict__ Gb,
                      float* __restrict__ out)
{
    const int p = blockIdx.x;          // pair index 0..2046
    const int b = blockIdx.y;          // batch 0..15
    const int t = threadIdx.x;         // 0..255, each handles 4 floats

    const size_t base = ((size_t)b * SEQ + (size_t)(2 * p)) * DIM;
    const float4* __restrict__ left4  = (const float4*)(X + base);
    const float4* __restrict__ mid4   = (const float4*)(X + base + DIM);
    const float4* __restrict__ right4 = (const float4*)(X + base + 2 * DIM);
    const float4* __restrict__ G4     = (const float4*)G;   // interleaved (d,2)

    // ---- gate dot products ----
    float4 m  = mid4[t];
    float4 ga = G4[2 * t];       // G[8t+0..3]  = {G[4t][0],G[4t][1],G[4t+1][0],G[4t+1][1]}
    float4 gc = G4[2 * t + 1];   // G[8t+4..7]
    float s0 = m.x * ga.x + m.y * ga.z + m.z * gc.x + m.w * gc.z;
    float s1 = m.x * ga.y + m.y * ga.w + m.z * gc.y + m.w * gc.w;

    // ---- issue left/right loads before the reduction barrier ----
    float4 L = left4[t];
    float4 R = right4[t];

    // ---- block reduce (8 warps) ----
    #pragma unroll
    for (int off = 16; off > 0; off >>= 1) {
        s0 += __shfl_xor_sync(0xFFFFFFFFu, s0, off);
        s1 += __shfl_xor_sync(0xFFFFFFFFu, s1, off);
    }
    __shared__ float sh0[8], sh1[8];
    __shared__ float g0_sh;
    const int warp = t >> 5, lane = t & 31;
    if (lane == 0) { sh0[warp] = s0; sh1[warp] = s1; }
    __syncthreads();
    if (t == 0) {
        float a = Gb[0], c = Gb[1];
        #pragma unroll
        for (int i = 0; i < 8; i++) { a += sh0[i]; c += sh1[i]; }
        // softmax over 2 logits: g0 = 1/(1+exp(c-a)); saturates correctly on overflow
        g0_sh = 1.0f / (1.0f + __expf(c - a));
    }
    __syncthreads();

    const float g0 = g0_sh;
    const float g1 = 1.0f - g0;

    float4 o;
    o.x = L.x * g0 + R.x * g1;
    o.y = L.y * g0 + R.y * g1;
    o.z = L.z * g0 + R.z * g1;
    o.w = L.w * g0 + R.w * g1;

    ((float4*)out)[((size_t)b * PAIRS + p) * (DIM / 4) + t] = o;
}

extern "C" void kernel_launch(void* const* d_in, const int* in_sizes, int n_in,
                              void* d_out, int out_size)
{
    const float* X  = (const float*)d_in[0];
    const float* G  = (const float*)d_in[1];
    const float* Gb = (const float*)d_in[2];
    float* out = (float*)d_out;

    dim3 grid(PAIRS, BATCH);
    gated_cnn_kernel<<<grid, 256>>>(X, G, Gb, out);
}